// round 1
// baseline (speedup 1.0000x reference)
#include <cuda_runtime.h>
#include <math.h>

#define NB 4096
#define LL 200
#define DD 128
#define HH 100
#define NTHREADS 256

// dynamic smem layout (in floats)
#define XS_OFF 0                   // x tile  [200][128]
#define WK_OFF (LL*DD)             // Wk      [128][100]   = 25600
#define QS_OFF (WK_OFF + DD*HH)    // q row   [128]        = 38400
#define QV_OFF (QS_OFF + DD)       // qv      [100] pad128 = 38528
#define BK_OFF (QV_OFF + 128)      // bk      [100] pad128 = 38656
#define VV_OFF (BK_OFF + 128)      // v       [100] pad128 = 38784
#define SS_OFF (VV_OFF + 128)      // scores/a/w [200]     = 38912
#define MK_OFF (SS_OFF + LL)       // mask    [200]        = 39112
#define SMEM_FLOATS (MK_OFF + LL)  //                      = 39312
#define SMEM_BYTES (SMEM_FLOATS * 4)   // 157248 B

__global__ void __launch_bounds__(NTHREADS, 1) mxqa_kernel(
    const float* __restrict__ x, const float* __restrict__ q,
    const float* __restrict__ Wk, const float* __restrict__ bk,
    const float* __restrict__ Wq, const float* __restrict__ v,
    float* __restrict__ out)
{
    extern __shared__ float sm[];
    float* xs  = sm + XS_OFF;
    float* wk  = sm + WK_OFF;
    float* qs  = sm + QS_OFF;
    float* qv  = sm + QV_OFF;
    float* bks = sm + BK_OFF;
    float* vvs = sm + VV_OFF;
    float* ss  = sm + SS_OFF;
    float* mk  = sm + MK_OFF;
    __shared__ float denom_sh;

    const int b    = blockIdx.x;
    const int tid  = threadIdx.x;
    const int lane = tid & 31;
    const int wid  = tid >> 5;

    // ---- stage x[b] (float4, coalesced) and Wk into smem ----
    {
        const float4* xg = reinterpret_cast<const float4*>(x + (size_t)b * (LL * DD));
        float4* xs4 = reinterpret_cast<float4*>(xs);
        #pragma unroll 1
        for (int i = tid; i < (LL * DD) / 4; i += NTHREADS) xs4[i] = xg[i];

        const float4* wg = reinterpret_cast<const float4*>(Wk);
        float4* wk4 = reinterpret_cast<float4*>(wk);
        #pragma unroll 1
        for (int i = tid; i < (DD * HH) / 4; i += NTHREADS) wk4[i] = wg[i];

        if (tid < DD / 4)
            reinterpret_cast<float4*>(qs)[tid] =
                reinterpret_cast<const float4*>(q + (size_t)b * DD)[tid];
        if (tid < HH) { bks[tid] = bk[tid]; vvs[tid] = v[tid]; }
        if (tid < LL) ss[tid] = 0.0f;
        if (tid == 0) denom_sh = 0.0f;
    }
    __syncthreads();

    // ---- qv[h] = q[b] . Wq[:,h]  (Wq stays hot in L2 across all 4096 CTAs) ----
    if (tid < HH) {
        float acc = 0.0f;
        #pragma unroll 8
        for (int d = 0; d < DD; d++) acc += qs[d] * __ldg(Wq + d * HH + tid);
        qv[tid] = acc;
    }

    // ---- mask[l] = any(x[b,l,:] != 0)  (warp per row, float4 + ballot) ----
    for (int l = wid; l < LL; l += NTHREADS / 32) {
        float4 xv = reinterpret_cast<const float4*>(xs + l * DD)[lane];
        bool nz = (xv.x != 0.0f) || (xv.y != 0.0f) || (xv.z != 0.0f) || (xv.w != 0.0f);
        unsigned bal = __ballot_sync(0xffffffffu, nz);
        if (lane == 0) mk[l] = bal ? 1.0f : 0.0f;
    }
    __syncthreads();

    // ---- main GEMM: S[l,h] = x[b,l,:] . Wk[:,h], 4x4 register tiles ----
    // 50 l-tiles x 25 h-tiles = 1250 tiles over 256 threads.
    for (int t = tid; t < (LL / 4) * (HH / 4); t += NTHREADS) {
        const int lt = t / (HH / 4);
        const int ht = t - lt * (HH / 4);
        const int l0 = lt * 4, h0 = ht * 4;
        float a[4][4] = {};
        #pragma unroll 8
        for (int d = 0; d < DD; d++) {
            const float4 wv = *reinterpret_cast<const float4*>(wk + d * HH + h0);
            const float x0 = xs[(l0 + 0) * DD + d];
            const float x1 = xs[(l0 + 1) * DD + d];
            const float x2 = xs[(l0 + 2) * DD + d];
            const float x3 = xs[(l0 + 3) * DD + d];
            a[0][0] += x0 * wv.x; a[0][1] += x0 * wv.y; a[0][2] += x0 * wv.z; a[0][3] += x0 * wv.w;
            a[1][0] += x1 * wv.x; a[1][1] += x1 * wv.y; a[1][2] += x1 * wv.z; a[1][3] += x1 * wv.w;
            a[2][0] += x2 * wv.x; a[2][1] += x2 * wv.y; a[2][2] += x2 * wv.z; a[2][3] += x2 * wv.w;
            a[3][0] += x3 * wv.x; a[3][1] += x3 * wv.y; a[3][2] += x3 * wv.z; a[3][3] += x3 * wv.w;
        }
        // fused epilogue: scores[l] += sum_j v[h0+j] * tanh(S + bk + qv)
        #pragma unroll
        for (int i = 0; i < 4; i++) {
            float p = 0.0f;
            #pragma unroll
            for (int j = 0; j < 4; j++)
                p += vvs[h0 + j] * tanhf(a[i][j] + bks[h0 + j] + qv[h0 + j]);
            atomicAdd(&ss[l0 + i], p);
        }
    }
    __syncthreads();

    // ---- a[l] = exp(scores[l]) * mask[l]; denom = sum_l a[l] ----
    if (tid < LL) ss[tid] = expf(ss[tid]) * mk[tid];
    __syncthreads();
    {
        float av = (tid < LL) ? ss[tid] : 0.0f;
        #pragma unroll
        for (int o = 16; o > 0; o >>= 1) av += __shfl_down_sync(0xffffffffu, av, o);
        if (lane == 0) atomicAdd(&denom_sh, av);
    }
    __syncthreads();
    const float inv = 1.0f / (denom_sh + 1e-7f);

    // ---- out[b,d] = (sum_l x[b,l,d] * a[l]) * inv ----
    if (tid < DD) {
        float acc = 0.0f;
        #pragma unroll 8
        for (int l = 0; l < LL; l++) acc += xs[l * DD + tid] * ss[l];
        out[(size_t)b * DD + tid] = acc * inv;
    }
}

extern "C" void kernel_launch(void* const* d_in, const int* in_sizes, int n_in,
                              void* d_out, int out_size)
{
    const float* x  = (const float*)d_in[0];
    const float* q  = (const float*)d_in[1];
    const float* Wk = (const float*)d_in[2];
    const float* bk = (const float*)d_in[3];
    const float* Wq = (const float*)d_in[4];
    const float* v  = (const float*)d_in[5];
    float* out = (float*)d_out;

    // Non-stream API; safe to call every launch (incl. under graph capture).
    cudaFuncSetAttribute(mxqa_kernel, cudaFuncAttributeMaxDynamicSharedMemorySize,
                         SMEM_BYTES);

    mxqa_kernel<<<NB, NTHREADS, SMEM_BYTES>>>(x, q, Wk, bk, Wq, v, out);
}

// round 2
// speedup vs baseline: 1.0149x; 1.0149x over previous
#include <cuda_runtime.h>
#include <math.h>

#define NB 4096
#define LL 200
#define DD 128
#define HH 100
#define NTHREADS 256

// dynamic smem layout (in floats)
#define XS_OFF 0                   // x tile  [200][128]        = 25600
#define WK_OFF (LL*DD)             // Wk      [128][100]        = 12800
#define QS_OFF (WK_OFF + DD*HH)    // q row   [128]
#define QV_OFF (QS_OFF + DD)       // qv+bk   [100] pad128
#define BK_OFF (QV_OFF + 128)      // bk      [100] pad128
#define VV_OFF (BK_OFF + 128)      // v       [100] pad128
#define SS_OFF (VV_OFF + 128)      // scores/a [200]
#define MK_OFF (SS_OFF + LL)       // mask    [200]
#define SMEM_FLOATS (MK_OFF + LL)
#define SMEM_BYTES (SMEM_FLOATS * 4)   // ~157 KB

__device__ __forceinline__ float htanh(float x) {
    float y;
    asm("tanh.approx.f32 %0, %1;" : "=f"(y) : "f"(x));
    return y;
}

__global__ void __launch_bounds__(NTHREADS, 1) mxqa_kernel(
    const float* __restrict__ x, const float* __restrict__ q,
    const float* __restrict__ Wk, const float* __restrict__ bk,
    const float* __restrict__ Wq, const float* __restrict__ v,
    float* __restrict__ out)
{
    extern __shared__ float sm[];
    float* xs  = sm + XS_OFF;
    float* wk  = sm + WK_OFF;
    float* qs  = sm + QS_OFF;
    float* qv  = sm + QV_OFF;   // will hold bk[h] + (q @ Wq)[h]
    float* bks = sm + BK_OFF;
    float* vvs = sm + VV_OFF;
    float* ss  = sm + SS_OFF;
    float* mk  = sm + MK_OFF;
    __shared__ float denom_sh;

    const int b    = blockIdx.x;
    const int tid  = threadIdx.x;
    const int lane = tid & 31;
    const int wid  = tid >> 5;

    // ---- stage x[b] (float4, coalesced) and Wk into smem ----
    {
        const float4* xg = reinterpret_cast<const float4*>(x + (size_t)b * (LL * DD));
        float4* xs4 = reinterpret_cast<float4*>(xs);
        #pragma unroll 1
        for (int i = tid; i < (LL * DD) / 4; i += NTHREADS) xs4[i] = xg[i];

        const float4* wg = reinterpret_cast<const float4*>(Wk);
        float4* wk4 = reinterpret_cast<float4*>(wk);
        #pragma unroll 1
        for (int i = tid; i < (DD * HH) / 4; i += NTHREADS) wk4[i] = wg[i];

        if (tid < DD / 4)
            reinterpret_cast<float4*>(qs)[tid] =
                reinterpret_cast<const float4*>(q + (size_t)b * DD)[tid];
        if (tid < HH) { bks[tid] = bk[tid]; vvs[tid] = v[tid]; }
        if (tid < LL) ss[tid] = 0.0f;
        if (tid == 0) denom_sh = 0.0f;
    }
    __syncthreads();

    // ---- qv[h] = bk[h] + q[b] . Wq[:,h]  (Wq hot in L2 across CTAs) ----
    if (tid < HH) {
        float acc = bks[tid];
        #pragma unroll 8
        for (int d = 0; d < DD; d++) acc += qs[d] * __ldg(Wq + d * HH + tid);
        qv[tid] = acc;
    }

    // ---- mask[l] = any(x[b,l,:] != 0)  (warp per row, float4 + ballot) ----
    for (int l = wid; l < LL; l += NTHREADS / 32) {
        float4 xv = reinterpret_cast<const float4*>(xs + l * DD)[lane];
        bool nz = (xv.x != 0.0f) || (xv.y != 0.0f) || (xv.z != 0.0f) || (xv.w != 0.0f);
        unsigned bal = __ballot_sync(0xffffffffu, nz);
        if (lane == 0) mk[l] = bal ? 1.0f : 0.0f;
    }
    __syncthreads();

    // ---- main GEMM: S[l,h] = x[b,l,:] . Wk[:,h] ----
    // 4x4 (l x h) register tiles, d vectorized by 4 (all LDS.128).
    // 50 l-tiles x 25 h-tiles = 1250 tiles over 256 threads (4.88/thread).
    for (int t = tid; t < (LL / 4) * (HH / 4); t += NTHREADS) {
        const int lt = t / (HH / 4);
        const int ht = t - lt * (HH / 4);
        const float* xp = xs + (lt * 4) * DD;
        const float* wp = wk + ht * 4;
        float a[4][4] = {};
        #pragma unroll 2
        for (int d = 0; d < DD; d += 4) {
            const float4 x0 = *reinterpret_cast<const float4*>(xp + 0 * DD + d);
            const float4 x1 = *reinterpret_cast<const float4*>(xp + 1 * DD + d);
            const float4 x2 = *reinterpret_cast<const float4*>(xp + 2 * DD + d);
            const float4 x3 = *reinterpret_cast<const float4*>(xp + 3 * DD + d);
            const float4 w0 = *reinterpret_cast<const float4*>(wp + (d + 0) * HH);
            const float4 w1 = *reinterpret_cast<const float4*>(wp + (d + 1) * HH);
            const float4 w2 = *reinterpret_cast<const float4*>(wp + (d + 2) * HH);
            const float4 w3 = *reinterpret_cast<const float4*>(wp + (d + 3) * HH);
            #define ROW(i, xv)                                                       \
                a[i][0] += xv.x * w0.x; a[i][1] += xv.x * w0.y;                      \
                a[i][2] += xv.x * w0.z; a[i][3] += xv.x * w0.w;                      \
                a[i][0] += xv.y * w1.x; a[i][1] += xv.y * w1.y;                      \
                a[i][2] += xv.y * w1.z; a[i][3] += xv.y * w1.w;                      \
                a[i][0] += xv.z * w2.x; a[i][1] += xv.z * w2.y;                      \
                a[i][2] += xv.z * w2.z; a[i][3] += xv.z * w2.w;                      \
                a[i][0] += xv.w * w3.x; a[i][1] += xv.w * w3.y;                      \
                a[i][2] += xv.w * w3.z; a[i][3] += xv.w * w3.w;
            ROW(0, x0) ROW(1, x1) ROW(2, x2) ROW(3, x3)
            #undef ROW
        }
        // fused epilogue: scores[l] += sum_j v[h0+j] * tanh(S + bk + qWq)
        const int l0 = lt * 4, h0 = ht * 4;
        const float bq0 = qv[h0 + 0], bq1 = qv[h0 + 1];
        const float bq2 = qv[h0 + 2], bq3 = qv[h0 + 3];
        const float v0 = vvs[h0 + 0], v1 = vvs[h0 + 1];
        const float v2 = vvs[h0 + 2], v3 = vvs[h0 + 3];
        #pragma unroll
        for (int i = 0; i < 4; i++) {
            float p = v0 * htanh(a[i][0] + bq0)
                    + v1 * htanh(a[i][1] + bq1)
                    + v2 * htanh(a[i][2] + bq2)
                    + v3 * htanh(a[i][3] + bq3);
            atomicAdd(&ss[l0 + i], p);
        }
    }
    __syncthreads();

    // ---- a[l] = exp(scores[l]) * mask[l]; denom = sum_l a[l] ----
    if (tid < LL) ss[tid] = __expf(ss[tid]) * mk[tid];
    __syncthreads();
    {
        float av = (tid < LL) ? ss[tid] : 0.0f;
        #pragma unroll
        for (int o = 16; o > 0; o >>= 1) av += __shfl_down_sync(0xffffffffu, av, o);
        if (lane == 0) atomicAdd(&denom_sh, av);
    }
    __syncthreads();
    const float inv = 1.0f / (denom_sh + 1e-7f);

    // ---- out[b,d] = (sum_l x[b,l,d] * a[l]) * inv ----
    if (tid < DD) {
        float acc = 0.0f;
        #pragma unroll 8
        for (int l = 0; l < LL; l++) acc += xs[l * DD + tid] * ss[l];
        out[(size_t)b * DD + tid] = acc * inv;
    }
}

extern "C" void kernel_launch(void* const* d_in, const int* in_sizes, int n_in,
                              void* d_out, int out_size)
{
    const float* x  = (const float*)d_in[0];
    const float* q  = (const float*)d_in[1];
    const float* Wk = (const float*)d_in[2];
    const float* bk = (const float*)d_in[3];
    const float* Wq = (const float*)d_in[4];
    const float* v  = (const float*)d_in[5];
    float* out = (float*)d_out;

    cudaFuncSetAttribute(mxqa_kernel, cudaFuncAttributeMaxDynamicSharedMemorySize,
                         SMEM_BYTES);
    mxqa_kernel<<<NB, NTHREADS, SMEM_BYTES>>>(x, q, Wk, bk, Wq, v, out);
}

// round 4
// speedup vs baseline: 2.0454x; 2.0154x over previous
#include <cuda_runtime.h>
#include <math.h>
#include <stdint.h>

#define NB 4096
#define LL 200
#define DD 128
#define HH 100
#define NTHREADS 256

#define MPAD 208            // 13 * 16
#define NPAD 112            // 14 * 8
#define XSTRIDE 132         // x smem row stride (floats): (4l+d)%32 distinct
#define BSTRIDE 120         // B smem row stride (floats): (24k+n)%32 distinct
#define MBLOCKS 13
#define NPAIRS 7            // 14 N-tiles of 8, processed in pairs
#define KSTEPS 16           // 128 / 8

// ---- smem layout (float indices) ----
#define XS_F 0                            // x  [208][132] = 27456
#define BB_F (XS_F + MPAD * XSTRIDE)      // Wk^T as tf32 [128][120] = 15360
#define QV_F (BB_F + DD * BSTRIDE)        // bk + qWq [112]
#define VV_F (QV_F + NPAD)                // v [112]
#define SS_F (VV_F + NPAD)                // a[l] [208]
#define MK_F (SS_F + MPAD)                // mask [208]
#define RD_F (MK_F + MPAD)                // cross-half reduce [128]
#define DN_F (RD_F + DD)                  // denom
#define SMEM_FLOATS (DN_F + 1)
#define SMEM_BYTES (SMEM_FLOATS * 4)      // ~174 KB

__device__ float g_qv[NB * NPAD];         // precomputed bk + q@Wq (padded, static scratch)

__device__ __forceinline__ float htanh(float x) {
    float y; asm("tanh.approx.f32 %0, %1;" : "=f"(y) : "f"(x)); return y;
}
__device__ __forceinline__ uint32_t f2tf32(float x) {
    uint32_t u; asm("cvt.rna.tf32.f32 %0, %1;" : "=r"(u) : "f"(x)); return u;
}
__device__ __forceinline__ void mma_tf32(float c[4], const uint32_t a[4],
                                         uint32_t b0, uint32_t b1) {
    asm volatile(
        "mma.sync.aligned.m16n8k8.row.col.f32.tf32.tf32.f32 "
        "{%0,%1,%2,%3}, {%4,%5,%6,%7}, {%8,%9}, {%0,%1,%2,%3};"
        : "+f"(c[0]), "+f"(c[1]), "+f"(c[2]), "+f"(c[3])
        : "r"(a[0]), "r"(a[1]), "r"(a[2]), "r"(a[3]), "r"(b0), "r"(b1));
}

// ---------- kernel 1: qv[b,h] = bk[h] + q[b,:] @ Wq[:,h] ----------
__global__ void __launch_bounds__(128) qv_kernel(
    const float* __restrict__ q, const float* __restrict__ Wq,
    const float* __restrict__ bk)
{
    __shared__ float qs[DD];
    const int b = blockIdx.x, tid = threadIdx.x;
    qs[tid] = q[(size_t)b * DD + tid];
    __syncthreads();
    if (tid < NPAD) {
        float acc = 0.0f;
        if (tid < HH) {
            acc = bk[tid];
            #pragma unroll 8
            for (int d = 0; d < DD; d++) acc += qs[d] * __ldg(Wq + d * HH + tid);
        }
        g_qv[(size_t)b * NPAD + tid] = acc;
    }
}

// ---------- kernel 2: main fused attention ----------
__global__ void __launch_bounds__(NTHREADS, 1) mxqa_kernel(
    const float* __restrict__ x, const float* __restrict__ Wk,
    const float* __restrict__ v, float* __restrict__ out)
{
    extern __shared__ __align__(16) float sm[];
    float* xs = sm + XS_F;
    uint32_t* bb = reinterpret_cast<uint32_t*>(sm + BB_F);
    float* qv = sm + QV_F;
    float* vv = sm + VV_F;
    float* ss = sm + SS_F;
    float* mk = sm + MK_F;
    float* rd = sm + RD_F;

    const int b    = blockIdx.x;
    const int tid  = threadIdx.x;
    const int lane = tid & 31;
    const int wid  = tid >> 5;

    if (tid == 0) sm[DN_F] = 0.0f;
    if (tid < NPAD) {
        qv[tid] = g_qv[(size_t)b * NPAD + tid];
        vv[tid] = (tid < HH) ? v[tid] : 0.0f;
    }

    // ---- stage x[b] (coalesced float4) + mask via ballot ----
    {
        const float4* xg = reinterpret_cast<const float4*>(x + (size_t)b * (LL * DD));
        #pragma unroll 1
        for (int i = tid; i < LL * (DD / 4); i += NTHREADS) {
            const int l = i >> 5, d4 = i & 31;        // whole warp shares l
            float4 xv = xg[i];
            *reinterpret_cast<float4*>(xs + l * XSTRIDE + d4 * 4) = xv;
            bool nz = (xv.x != 0.f) || (xv.y != 0.f) || (xv.z != 0.f) || (xv.w != 0.f);
            unsigned bal = __ballot_sync(0xffffffffu, nz);
            if (lane == 0) mk[l] = bal ? 1.0f : 0.0f;
        }
    }
    // ---- stage Wk^T as tf32, zero-padded cols [100,112) ----
    #pragma unroll 1
    for (int d = wid; d < DD; d += 8) {
        for (int n = lane; n < NPAD; n += 32) {
            float val = (n < HH) ? __ldg(Wk + d * HH + n) : 0.0f;
            bb[d * BSTRIDE + n] = f2tf32(val);
        }
    }
    __syncthreads();

    // ---- GEMM + fused epilogue: warp handles M-blocks wid, wid+8 ----
    const int g = lane >> 2;          // group id (row within block)
    const int t = lane & 3;           // thread-in-group (col quad)
    for (int mb = wid; mb < MBLOCKS; mb += 8) {
        const int row0 = mb * 16 + g;
        // cache A fragments for this M-block (rows 192..207 of mb=12 may be
        // garbage smem — their outputs are discarded below)
        uint32_t Ar[KSTEPS][4];
        #pragma unroll
        for (int ks = 0; ks < KSTEPS; ks++) {
            const int c = ks * 8 + t;
            Ar[ks][0] = f2tf32(xs[row0 * XSTRIDE + c]);
            Ar[ks][1] = f2tf32(xs[(row0 + 8) * XSTRIDE + c]);
            Ar[ks][2] = f2tf32(xs[row0 * XSTRIDE + c + 4]);
            Ar[ks][3] = f2tf32(xs[(row0 + 8) * XSTRIDE + c + 4]);
        }
        float sc_lo = 0.0f, sc_hi = 0.0f;
        #pragma unroll 1
        for (int np = 0; np < NPAIRS; np++) {
            float c0[4] = {0.f, 0.f, 0.f, 0.f};
            float c1[4] = {0.f, 0.f, 0.f, 0.f};
            const int ncol = np * 16 + g;
            #pragma unroll
            for (int ks = 0; ks < KSTEPS; ks++) {
                const int krow = ks * 8 + t;
                const uint32_t b00 = bb[krow * BSTRIDE + ncol];
                const uint32_t b01 = bb[(krow + 4) * BSTRIDE + ncol];
                const uint32_t b10 = bb[krow * BSTRIDE + ncol + 8];
                const uint32_t b11 = bb[(krow + 4) * BSTRIDE + ncol + 8];
                mma_tf32(c0, Ar[ks], b00, b01);
                mma_tf32(c1, Ar[ks], b10, b11);
            }
            // consume: cols h0,h0+1 (tile0) and h0+8,h0+9 (tile1); pads have
            // B==0 => S==0, vv==0 => contribution 0 (no NaN possible)
            const int h0 = np * 16 + 2 * t;
            sc_lo += vv[h0] * htanh(c0[0] + qv[h0])
                   + vv[h0 + 1] * htanh(c0[1] + qv[h0 + 1]);
            sc_hi += vv[h0] * htanh(c0[2] + qv[h0])
                   + vv[h0 + 1] * htanh(c0[3] + qv[h0 + 1]);
            sc_lo += vv[h0 + 8] * htanh(c1[0] + qv[h0 + 8])
                   + vv[h0 + 9] * htanh(c1[1] + qv[h0 + 9]);
            sc_hi += vv[h0 + 8] * htanh(c1[2] + qv[h0 + 8])
                   + vv[h0 + 9] * htanh(c1[3] + qv[h0 + 9]);
        }
        // reduce partial h-sums across the 4 lanes of each row group
        sc_lo += __shfl_xor_sync(0xffffffffu, sc_lo, 1);
        sc_lo += __shfl_xor_sync(0xffffffffu, sc_lo, 2);
        sc_hi += __shfl_xor_sync(0xffffffffu, sc_hi, 1);
        sc_hi += __shfl_xor_sync(0xffffffffu, sc_hi, 2);
        if (t == 0) {
            const int r = row0;
            ss[r]     = (r < LL)     ? __expf(sc_lo) * mk[r]     : 0.0f;
            ss[r + 8] = (r + 8 < LL) ? __expf(sc_hi) * mk[r + 8] : 0.0f;
        }
    }
    __syncthreads();

    // ---- denominator ----
    {
        float av = (tid < MPAD) ? ss[tid] : 0.0f;
        #pragma unroll
        for (int o = 16; o > 0; o >>= 1) av += __shfl_down_sync(0xffffffffu, av, o);
        if (lane == 0) atomicAdd(&sm[DN_F], av);
    }
    __syncthreads();
    const float inv = 1.0f / (sm[DN_F] + 1e-7f);

    // ---- out[b,d] = inv * sum_l x[l,d]*a[l]  (two thread halves over l) ----
    {
        const int d = tid & 127, half = tid >> 7;
        const int l0 = half * 100;
        float acc = 0.0f;
        #pragma unroll 4
        for (int l = l0; l < l0 + 100; l++)
            acc += xs[l * XSTRIDE + d] * ss[l];
        if (half) rd[d] = acc;
        __syncthreads();
        if (!half) out[(size_t)b * DD + d] = (acc + rd[d]) * inv;
    }
}

extern "C" void kernel_launch(void* const* d_in, const int* in_sizes, int n_in,
                              void* d_out, int out_size)
{
    const float* x  = (const float*)d_in[0];
    const float* q  = (const float*)d_in[1];
    const float* Wk = (const float*)d_in[2];
    const float* bk = (const float*)d_in[3];
    const float* Wq = (const float*)d_in[4];
    const float* v  = (const float*)d_in[5];
    float* out = (float*)d_out;

    cudaFuncSetAttribute(mxqa_kernel, cudaFuncAttributeMaxDynamicSharedMemorySize,
                         SMEM_BYTES);
    qv_kernel<<<NB, 128>>>(q, Wq, bk);
    mxqa_kernel<<<NB, NTHREADS, SMEM_BYTES>>>(x, Wk, v, out);
}

// round 8
// speedup vs baseline: 3.2473x; 1.5876x over previous
#include <cuda_runtime.h>
#include <math.h>
#include <stdint.h>

#define NB 4096
#define LL 200
#define DD 128
#define HH 100
#define NTHREADS 512

#define MPAD 208            // 13 * 16
#define NPAD 112            // 14 * 8
#define XSTRIDE 132         // x smem row stride (floats)
#define BSTRIDE 120         // B smem row stride (floats)
#define MBLOCKS 13
#define NPAIRS 7            // 14 N-tiles of 8, processed in pairs
#define KSTEPS 16           // 128 / 8

// ---- smem layout (float indices) ----
#define XS_F 0                            // x  [208][132] = 27456
#define BB_F (XS_F + MPAD * XSTRIDE)      // Wk^T as tf32 [128][120] = 15360
#define QV_F (BB_F + DD * BSTRIDE)        // bk + qWq [112]
#define VV_F (QV_F + NPAD)                // v [112]
#define SS_F (VV_F + NPAD)                // a[l] [208]
#define MK_F (SS_F + MPAD)                // mask [208]
#define RD_F (MK_F + MPAD)                // quarter partials [4*128]
#define DN_F (RD_F + 4 * DD)              // denom
#define SMEM_FLOATS (DN_F + 1)
#define SMEM_BYTES (SMEM_FLOATS * 4)      // ~176 KB

__device__ float g_qv[NB * NPAD];         // precomputed bk + q@Wq

__device__ __forceinline__ float htanh(float x) {
    float y; asm("tanh.approx.f32 %0, %1;" : "=f"(y) : "f"(x)); return y;
}
__device__ __forceinline__ uint32_t f2tf32(float x) {
    uint32_t u; asm("cvt.rna.tf32.f32 %0, %1;" : "=r"(u) : "f"(x)); return u;
}
__device__ __forceinline__ void mma_tf32(float c[4], const uint32_t a[4],
                                         uint32_t b0, uint32_t b1) {
    asm volatile(
        "mma.sync.aligned.m16n8k8.row.col.f32.tf32.tf32.f32 "
        "{%0,%1,%2,%3}, {%4,%5,%6,%7}, {%8,%9}, {%0,%1,%2,%3};"
        : "+f"(c[0]), "+f"(c[1]), "+f"(c[2]), "+f"(c[3])
        : "r"(a[0]), "r"(a[1]), "r"(a[2]), "r"(a[3]), "r"(b0), "r"(b1));
}

// ---------- kernel 1: qv[b,h] = bk[h] + q[b,:] @ Wq[:,h] ----------
__global__ void __launch_bounds__(128) qv_kernel(
    const float* __restrict__ q, const float* __restrict__ Wq,
    const float* __restrict__ bk)
{
    __shared__ float qs[DD];
    const int b = blockIdx.x, tid = threadIdx.x;
    qs[tid] = q[(size_t)b * DD + tid];
    __syncthreads();
    if (tid < NPAD) {
        float acc = 0.0f;
        if (tid < HH) {
            acc = bk[tid];
            #pragma unroll 8
            for (int d = 0; d < DD; d++) acc += qs[d] * __ldg(Wq + d * HH + tid);
        }
        g_qv[(size_t)b * NPAD + tid] = acc;
    }
}

// ---------- kernel 2: main fused attention ----------
__global__ void __launch_bounds__(NTHREADS, 1) mxqa_kernel(
    const float* __restrict__ x, const float* __restrict__ Wk,
    const float* __restrict__ v, float* __restrict__ out)
{
    extern __shared__ __align__(16) float sm[];
    float* xs = sm + XS_F;
    uint32_t* bb = reinterpret_cast<uint32_t*>(sm + BB_F);
    float* qv = sm + QV_F;
    float* vv = sm + VV_F;
    float* ss = sm + SS_F;
    float* mk = sm + MK_F;
    float* rd = sm + RD_F;

    const int b    = blockIdx.x;
    const int tid  = threadIdx.x;
    const int lane = tid & 31;
    const int wid  = tid >> 5;

    if (tid == 0) sm[DN_F] = 0.0f;
    if (tid < NPAD) {
        qv[tid] = g_qv[(size_t)b * NPAD + tid];
        vv[tid] = (tid < HH) ? v[tid] : 0.0f;
    }

    // ---- stage x[b] (coalesced float4) + mask via ballot ----
    {
        const float4* xg = reinterpret_cast<const float4*>(x + (size_t)b * (LL * DD));
        #pragma unroll 1
        for (int i = tid; i < LL * (DD / 4); i += NTHREADS) {
            const int l = i >> 5, d4 = i & 31;        // whole warp shares l
            float4 xv = xg[i];
            *reinterpret_cast<float4*>(xs + l * XSTRIDE + d4 * 4) = xv;
            bool nz = (xv.x != 0.f) || (xv.y != 0.f) || (xv.z != 0.f) || (xv.w != 0.f);
            unsigned bal = __ballot_sync(0xffffffffu, nz);
            if (lane == 0) mk[l] = bal ? 1.0f : 0.0f;
        }
    }
    // ---- stage Wk^T as tf32, zero-padded cols [100,112) ----
    #pragma unroll 1
    for (int d = wid; d < DD; d += NTHREADS / 32) {
        for (int n = lane; n < NPAD; n += 32) {
            float val = (n < HH) ? __ldg(Wk + d * HH + n) : 0.0f;
            bb[d * BSTRIDE + n] = f2tf32(val);
        }
    }
    __syncthreads();

    // ---- GEMM + fused epilogue: one M-block per warp (wid < 13) ----
    const int g = lane >> 2;          // group id (row within block)
    const int t = lane & 3;           // thread-in-group (col quad)
    if (wid < MBLOCKS) {
        const int mb = wid;
        const int row0 = mb * 16 + g;
        // cache A fragments for this M-block (pad rows produce discarded output)
        uint32_t Ar[KSTEPS][4];
        #pragma unroll
        for (int ks = 0; ks < KSTEPS; ks++) {
            const int c = ks * 8 + t;
            Ar[ks][0] = f2tf32(xs[row0 * XSTRIDE + c]);
            Ar[ks][1] = f2tf32(xs[(row0 + 8) * XSTRIDE + c]);
            Ar[ks][2] = f2tf32(xs[row0 * XSTRIDE + c + 4]);
            Ar[ks][3] = f2tf32(xs[(row0 + 8) * XSTRIDE + c + 4]);
        }
        float sc_lo = 0.0f, sc_hi = 0.0f;
        #pragma unroll 1
        for (int np = 0; np < NPAIRS; np++) {
            float c0[4] = {0.f, 0.f, 0.f, 0.f};
            float c1[4] = {0.f, 0.f, 0.f, 0.f};
            const int ncol = np * 16 + g;
            #pragma unroll
            for (int ks = 0; ks < KSTEPS; ks++) {
                const int krow = ks * 8 + t;
                const uint32_t b00 = bb[krow * BSTRIDE + ncol];
                const uint32_t b01 = bb[(krow + 4) * BSTRIDE + ncol];
                const uint32_t b10 = bb[krow * BSTRIDE + ncol + 8];
                const uint32_t b11 = bb[(krow + 4) * BSTRIDE + ncol + 8];
                mma_tf32(c0, Ar[ks], b00, b01);
                mma_tf32(c1, Ar[ks], b10, b11);
            }
            const int h0 = np * 16 + 2 * t;
            sc_lo += vv[h0] * htanh(c0[0] + qv[h0])
                   + vv[h0 + 1] * htanh(c0[1] + qv[h0 + 1]);
            sc_hi += vv[h0] * htanh(c0[2] + qv[h0])
                   + vv[h0 + 1] * htanh(c0[3] + qv[h0 + 1]);
            sc_lo += vv[h0 + 8] * htanh(c1[0] + qv[h0 + 8])
                   + vv[h0 + 9] * htanh(c1[1] + qv[h0 + 9]);
            sc_hi += vv[h0 + 8] * htanh(c1[2] + qv[h0 + 8])
                   + vv[h0 + 9] * htanh(c1[3] + qv[h0 + 9]);
        }
        // reduce partial h-sums across the 4 lanes of each row group
        sc_lo += __shfl_xor_sync(0xffffffffu, sc_lo, 1);
        sc_lo += __shfl_xor_sync(0xffffffffu, sc_lo, 2);
        sc_hi += __shfl_xor_sync(0xffffffffu, sc_hi, 1);
        sc_hi += __shfl_xor_sync(0xffffffffu, sc_hi, 2);
        if (t == 0) {
            const int r = row0;
            ss[r]     = (r < LL)     ? __expf(sc_lo) * mk[r]     : 0.0f;
            ss[r + 8] = (r + 8 < LL) ? __expf(sc_hi) * mk[r + 8] : 0.0f;
        }
    }
    __syncthreads();

    // ---- denominator ----
    {
        float av = (tid < MPAD) ? ss[tid] : 0.0f;
        #pragma unroll
        for (int o = 16; o > 0; o >>= 1) av += __shfl_down_sync(0xffffffffu, av, o);
        if (lane == 0 && wid < MPAD / 32 + 1) atomicAdd(&sm[DN_F], av);
    }
    __syncthreads();
    const float inv = 1.0f / (sm[DN_F] + 1e-7f);

    // ---- out[b,d] = inv * sum_l x[l,d]*a[l]  (four l-quarters) ----
    {
        const int d = tid & 127, quarter = tid >> 7;
        const int l0 = quarter * 50;
        float acc = 0.0f;
        #pragma unroll 5
        for (int l = l0; l < l0 + 50; l++)
            acc += xs[l * XSTRIDE + d] * ss[l];
        rd[quarter * DD + d] = acc;
        __syncthreads();
        if (quarter == 0)
            out[(size_t)b * DD + d] =
                (rd[d] + rd[DD + d] + rd[2 * DD + d] + rd[3 * DD + d]) * inv;
    }
}

extern "C" void kernel_launch(void* const* d_in, const int* in_sizes, int n_in,
                              void* d_out, int out_size)
{
    const float* x  = (const float*)d_in[0];
    const float* q  = (const float*)d_in[1];
    const float* Wk = (const float*)d_in[2];
    const float* bk = (const float*)d_in[3];
    const float* Wq = (const float*)d_in[4];
    const float* v  = (const float*)d_in[5];
    float* out = (float*)d_out;

    cudaFuncSetAttribute(mxqa_kernel, cudaFuncAttributeMaxDynamicSharedMemorySize,
                         SMEM_BYTES);
    qv_kernel<<<NB, 128>>>(q, Wq, bk);
    mxqa_kernel<<<NB, NTHREADS, SMEM_BYTES>>>(x, Wk, v, out);
}